// round 1
// baseline (speedup 1.0000x reference)
#include <cuda_runtime.h>
#include <cuda_bf16.h>

#define N_V 4096
#define N_E 8192
#define HD  128
#define ATOM_DIM 64
#define BOND_DIM 32
#define N_LAYER 4

// ---------------------------------------------------------------------------
// Scratch (static device globals; no allocations allowed)
// ---------------------------------------------------------------------------
__device__ float g_tmp[N_E * HD];   // intermediate for the 2-layer linears (max M = N_E)
__device__ float g_he [N_E * HD];   // edge features after e_linear
__device__ float g_hvA[N_V * HD];   // current hv
__device__ float g_hvB[N_V * HD];   // hv accumulator (hv + scatter-add target)
__device__ int   g_src[N_E];
__device__ int   g_dst[N_E];

// ---------------------------------------------------------------------------
// 1) Extract src/dst indices from the one-hot incidence matrices.
//    vewX is [N_V, N_E] row-major; column e has exactly one 1.0 at row src/dst.
//    Single streaming pass over both matrices (256 MB) with float4 loads.
// ---------------------------------------------------------------------------
__global__ void extract_idx_kernel(const float* __restrict__ vew1,
                                   const float* __restrict__ vew2,
                                   int* __restrict__ src, int* __restrict__ dst)
{
    const long long per_mat = (long long)N_V * N_E / 4;  // float4 count per matrix
    const long long total   = 2 * per_mat;
    long long stride = (long long)gridDim.x * blockDim.x;
    for (long long i = (long long)blockIdx.x * blockDim.x + threadIdx.x;
         i < total; i += stride) {
        const float* base = (i < per_mat) ? vew1 : vew2;
        int*         outp = (i < per_mat) ? src  : dst;
        long long p = (i < per_mat) ? i : (i - per_mat);
        float4 v = reinterpret_cast<const float4*>(base)[p];
        if (v.x != 0.0f || v.y != 0.0f || v.z != 0.0f || v.w != 0.0f) {
            long long lin = p * 4;
            int row = (int)(lin >> 13);        // / N_E (8192)
            int col = (int)(lin & (N_E - 1));  // % N_E  (N_E % 4 == 0, so same row)
            if (v.x != 0.0f) outp[col + 0] = row;
            if (v.y != 0.0f) outp[col + 1] = row;
            if (v.z != 0.0f) outp[col + 2] = row;
            if (v.w != 0.0f) outp[col + 3] = row;
        }
    }
}

// ---------------------------------------------------------------------------
// 2) Fused GEMM + bias + activation:  C[M,128] = act(A[M,K] @ W[128,K]^T + b)
//    Register-tiled SGEMM: BM=64, BN=128(=full N), BK=16, 256 threads,
//    each thread computes a 4x8 micro-tile. Optional second output C2
//    (used to keep hv and its accumulator copy in sync without extra copies).
//    ACT: 0 = leaky_relu(0.01), 1 = tanh
// ---------------------------------------------------------------------------
template<int K, int ACT>
__global__ __launch_bounds__(256)
void gemm_act_kernel(const float* __restrict__ A, const float* __restrict__ W,
                     const float* __restrict__ bias,
                     float* __restrict__ C, float* __restrict__ C2)
{
    constexpr int BM = 64, BN = 128, BK = 16;
    __shared__ float As[BK][BM];
    __shared__ float Ws[BK][BN];

    const int tid = threadIdx.x;        // 0..255
    const int tx  = tid & 15;           // column group: cols [tx*8, tx*8+8)
    const int ty  = tid >> 4;           // row group:    rows [ty*4, ty*4+4)
    const int m0  = blockIdx.x * BM;

    float acc[4][8];
#pragma unroll
    for (int i = 0; i < 4; i++)
#pragma unroll
        for (int j = 0; j < 8; j++) acc[i][j] = 0.0f;

#pragma unroll
    for (int k0 = 0; k0 < K; k0 += BK) {
        // --- load A tile (64x16) : one float4 per thread ---
        {
            int j0 = tid * 4;           // 0..1020
            int m  = j0 >> 4;           // row within tile
            int k  = j0 & 15;           // k offset (multiple of 4)
            float4 a4 = *reinterpret_cast<const float4*>(&A[(long long)(m0 + m) * K + k0 + k]);
            As[k + 0][m] = a4.x;
            As[k + 1][m] = a4.y;
            As[k + 2][m] = a4.z;
            As[k + 3][m] = a4.w;
        }
        // --- load W tile transposed: Ws[k][n] = W[n*K + k0 + k], two float4 per thread ---
        {
            int j0 = tid * 8;           // 0..2040
            int n  = j0 >> 4;           // 0..127
            int kk = j0 & 15;           // 0 or 8
            const float* wrow = &W[(long long)n * K + k0 + kk];
            float4 w0 = *reinterpret_cast<const float4*>(wrow);
            float4 w1 = *reinterpret_cast<const float4*>(wrow + 4);
            Ws[kk + 0][n] = w0.x; Ws[kk + 1][n] = w0.y;
            Ws[kk + 2][n] = w0.z; Ws[kk + 3][n] = w0.w;
            Ws[kk + 4][n] = w1.x; Ws[kk + 5][n] = w1.y;
            Ws[kk + 6][n] = w1.z; Ws[kk + 7][n] = w1.w;
        }
        __syncthreads();

#pragma unroll
        for (int k = 0; k < BK; k++) {
            float4 a4 = *reinterpret_cast<const float4*>(&As[k][ty * 4]);
            float a[4] = {a4.x, a4.y, a4.z, a4.w};
            float4 w0 = *reinterpret_cast<const float4*>(&Ws[k][tx * 8]);
            float4 w1 = *reinterpret_cast<const float4*>(&Ws[k][tx * 8 + 4]);
            float w[8] = {w0.x, w0.y, w0.z, w0.w, w1.x, w1.y, w1.z, w1.w};
#pragma unroll
            for (int i = 0; i < 4; i++)
#pragma unroll
                for (int j = 0; j < 8; j++)
                    acc[i][j] = fmaf(a[i], w[j], acc[i][j]);
        }
        __syncthreads();
    }

    // --- epilogue: bias + activation + (dual) store ---
    float b[8];
#pragma unroll
    for (int j = 0; j < 8; j++) b[j] = bias[tx * 8 + j];

#pragma unroll
    for (int i = 0; i < 4; i++) {
        int m = m0 + ty * 4 + i;
        float out[8];
#pragma unroll
        for (int j = 0; j < 8; j++) {
            float v = acc[i][j] + b[j];
            if (ACT == 0) v = (v > 0.0f) ? v : 0.01f * v;   // leaky_relu
            else          v = tanhf(v);                      // tanh
            out[j] = v;
        }
        float* crow = &C[(long long)m * HD + tx * 8];
        *reinterpret_cast<float4*>(crow)     = make_float4(out[0], out[1], out[2], out[3]);
        *reinterpret_cast<float4*>(crow + 4) = make_float4(out[4], out[5], out[6], out[7]);
        if (C2) {
            float* c2row = &C2[(long long)m * HD + tx * 8];
            *reinterpret_cast<float4*>(c2row)     = make_float4(out[0], out[1], out[2], out[3]);
            *reinterpret_cast<float4*>(c2row + 4) = make_float4(out[4], out[5], out[6], out[7]);
        }
    }
}

// ---------------------------------------------------------------------------
// 3) Per-layer edge op: hv_acc[src[e]] += relu(he[e] + hv[dst[e]])
//    (hv_acc must already contain the current hv). 2 edges per block, 256 thr.
// ---------------------------------------------------------------------------
__global__ __launch_bounds__(256)
void edge_kernel(const float* __restrict__ he, const float* __restrict__ hv,
                 float* __restrict__ hv_acc,
                 const int* __restrict__ src, const int* __restrict__ dst)
{
    int e = blockIdx.x * 2 + (threadIdx.x >> 7);
    int t = threadIdx.x & 127;
    int s = __ldg(&src[e]);
    int d = __ldg(&dst[e]);
    float v = he[(long long)e * HD + t] + hv[(long long)d * HD + t];
    v = fmaxf(v, 0.0f);
    atomicAdd(&hv_acc[(long long)s * HD + t], v);
}

// ---------------------------------------------------------------------------
// 4) Final he_out = concat(hv[src[e]], hv[dst[e]], he[e])  -> [N_E, 3H]
// ---------------------------------------------------------------------------
__global__ __launch_bounds__(128)
void he_out_kernel(const float* __restrict__ hv, const float* __restrict__ he,
                   const int* __restrict__ src, const int* __restrict__ dst,
                   float* __restrict__ out)
{
    int e = blockIdx.x;
    int t = threadIdx.x;   // 0..127
    int s = __ldg(&src[e]);
    int d = __ldg(&dst[e]);
    float* orow = &out[(long long)e * (3 * HD)];
    orow[t]            = hv[(long long)s * HD + t];
    orow[HD + t]       = hv[(long long)d * HD + t];
    orow[2 * HD + t]   = he[(long long)e * HD + t];
}

// ---------------------------------------------------------------------------
// Launcher
// ---------------------------------------------------------------------------
extern "C" void kernel_launch(void* const* d_in, const int* in_sizes, int n_in,
                              void* d_out, int out_size)
{
    const float* atom = (const float*)d_in[0];
    const float* bond = (const float*)d_in[1];
    const float* vew1 = (const float*)d_in[2];
    const float* vew2 = (const float*)d_in[3];
    const float* vW1  = (const float*)d_in[4];
    const float* vb1  = (const float*)d_in[5];
    const float* vW2  = (const float*)d_in[6];
    const float* vb2  = (const float*)d_in[7];
    const float* eW1  = (const float*)d_in[8];
    const float* eb1  = (const float*)d_in[9];
    const float* eW2  = (const float*)d_in[10];
    const float* eb2  = (const float*)d_in[11];
    const float* mlpW = (const float*)d_in[12];
    const float* mlpb = (const float*)d_in[13];

    float *tmp, *he, *hvA, *hvB;
    int *src, *dst;
    cudaGetSymbolAddress((void**)&tmp, g_tmp);
    cudaGetSymbolAddress((void**)&he,  g_he);
    cudaGetSymbolAddress((void**)&hvA, g_hvA);
    cudaGetSymbolAddress((void**)&hvB, g_hvB);
    cudaGetSymbolAddress((void**)&src, g_src);
    cudaGetSymbolAddress((void**)&dst, g_dst);

    float* hv_out = (float*)d_out;                 // [N_V, H]
    float* he_out = (float*)d_out + (long long)N_V * HD;  // [N_E, 3H]

    // 1) indices from one-hot incidence matrices (independent; overlaps with linears)
    extract_idx_kernel<<<2048, 256>>>(vew1, vew2, src, dst);

    // 2) v_linear: hv = tanh(leaky(atom @ vW1^T + vb1) @ vW2^T + vb2)
    gemm_act_kernel<ATOM_DIM, 0><<<N_V / 64, 256>>>(atom, vW1, vb1, tmp, nullptr);
    gemm_act_kernel<HD, 1><<<N_V / 64, 256>>>(tmp, vW2, vb2, hvA, hvB);  // hvB = copy for accumulation

    // 3) e_linear: he = tanh(leaky(bond @ eW1^T + eb1) @ eW2^T + eb2)
    gemm_act_kernel<BOND_DIM, 0><<<N_E / 64, 256>>>(bond, eW1, eb1, tmp, nullptr);
    gemm_act_kernel<HD, 1><<<N_E / 64, 256>>>(tmp, eW2, eb2, he, nullptr);

    // 4) message-passing layers
    for (int l = 0; l < N_LAYER; l++) {
        // hvB (== hv) += scatter_src( relu(he + hv[dst]) )
        edge_kernel<<<N_E / 2, 256>>>(he, hvA, hvB, src, dst);
        // hv = leaky(hvB @ mlp_W[l]^T + mlp_b[l]); keep accumulator copy in hvB
        float* c2 = (l == N_LAYER - 1) ? hv_out : hvB;
        gemm_act_kernel<HD, 0><<<N_V / 64, 256>>>(hvB, mlpW + (long long)l * HD * HD,
                                                  mlpb + (long long)l * HD, hvA, c2);
    }

    // 5) he_out = [hv[src] | hv[dst] | he]
    he_out_kernel<<<N_E, 128>>>(hvA, he, src, dst, he_out);
}

// round 2
// speedup vs baseline: 1.2627x; 1.2627x over previous
#include <cuda_runtime.h>
#include <cuda_bf16.h>

#define N_V 4096
#define N_E 8192
#define HD  128
#define ATOM_DIM 64
#define BOND_DIM 32
#define N_LAYER 4

// ---------------------------------------------------------------------------
// Scratch
// ---------------------------------------------------------------------------
__device__ float g_tmpv[N_V * HD];
__device__ float g_tmpe[N_E * HD];
__device__ float g_he  [N_E * HD];
__device__ float g_hvA [N_V * HD];
__device__ float g_hvB [N_V * HD];
__device__ int   g_src [N_E];
__device__ int   g_dst [N_E];

// ---------------------------------------------------------------------------
// One-hot scan body: find the nonzero row of each column of a [N_V, N_E]
// row-major matrix. One full matrix per call (8M float4 = 128 MB).
// 1024 blocks x 256 threads, 8 outer iters, 4 independent loads each (MLP=4).
// ---------------------------------------------------------------------------
__device__ __forceinline__ void proc_f4(float4 v, int p, int* __restrict__ outp)
{
    if (v.x != 0.0f || v.y != 0.0f || v.z != 0.0f || v.w != 0.0f) {
        int lin = p << 2;
        int row = lin >> 13;          // / N_E
        int col = lin & (N_E - 1);    // % N_E
        if (v.x != 0.0f) outp[col + 0] = row;
        if (v.y != 0.0f) outp[col + 1] = row;
        if (v.z != 0.0f) outp[col + 2] = row;
        if (v.w != 0.0f) outp[col + 3] = row;
    }
}

#define XB_BLOCKS 1024

__device__ void extract_body(const float* __restrict__ mat,
                             int* __restrict__ outp, int xb)
{
    const int PER = N_V * (N_E / 4);          // 8,388,608 float4 per matrix
    const int T   = XB_BLOCKS * 256;          // 262,144 threads
    const float4* m4 = reinterpret_cast<const float4*>(mat);
    int base = xb * 256 + threadIdx.x;
    for (int i = base; i < PER; i += 4 * T) {
        float4 v0 = __ldg(&m4[i]);
        float4 v1 = __ldg(&m4[i + T]);
        float4 v2 = __ldg(&m4[i + 2 * T]);
        float4 v3 = __ldg(&m4[i + 3 * T]);
        proc_f4(v0, i,         outp);
        proc_f4(v1, i + T,     outp);
        proc_f4(v2, i + 2 * T, outp);
        proc_f4(v3, i + 3 * T, outp);
    }
}

// ---------------------------------------------------------------------------
// Register-tiled GEMM body: C[BM,128] = act(A[BM,K] @ W[128,K]^T + b)
// 256 threads. BM=64 -> 4x8/thread, BM=32 -> 2x8/thread.
// ACT: 0 = leaky_relu(0.01), 1 = tanh
// ---------------------------------------------------------------------------
template<int BM, int K, int ACT>
__device__ __forceinline__ void gemm_body(const float* __restrict__ A,
                                          const float* __restrict__ W,
                                          const float* __restrict__ bias,
                                          float* __restrict__ C,
                                          float* __restrict__ C2,
                                          int m0, float* sA, float* sW)
{
    constexpr int BK = 16, BN = 128;
    constexpr int R  = BM / 16;               // rows per thread (4 or 2)
    const int tid = threadIdx.x;
    const int tx  = tid & 15;                 // cols [tx*8, tx*8+8)
    const int ty  = tid >> 4;                 // rows [ty*R, ty*R+R)

    float acc[R][8];
#pragma unroll
    for (int i = 0; i < R; i++)
#pragma unroll
        for (int j = 0; j < 8; j++) acc[i][j] = 0.0f;

#pragma unroll
    for (int k0 = 0; k0 < K; k0 += BK) {
        // A tile (BM x BK), R floats per thread
        if (R == 4) {
            int j0 = tid * 4, m = j0 >> 4, k = j0 & 15;
            float4 a4 = *reinterpret_cast<const float4*>(&A[(m0 + m) * K + k0 + k]);
            sA[(k + 0) * BM + m] = a4.x; sA[(k + 1) * BM + m] = a4.y;
            sA[(k + 2) * BM + m] = a4.z; sA[(k + 3) * BM + m] = a4.w;
        } else {
            int j0 = tid * 2, m = j0 >> 4, k = j0 & 15;
            float2 a2 = *reinterpret_cast<const float2*>(&A[(m0 + m) * K + k0 + k]);
            sA[(k + 0) * BM + m] = a2.x; sA[(k + 1) * BM + m] = a2.y;
        }
        // W tile transposed: sW[k][n] = W[n*K + k0 + k]
        {
            int j0 = tid * 8, n = j0 >> 4, kk = j0 & 15;
            const float* wr = &W[n * K + k0 + kk];
            float4 w0 = *reinterpret_cast<const float4*>(wr);
            float4 w1 = *reinterpret_cast<const float4*>(wr + 4);
            sW[(kk + 0) * BN + n] = w0.x; sW[(kk + 1) * BN + n] = w0.y;
            sW[(kk + 2) * BN + n] = w0.z; sW[(kk + 3) * BN + n] = w0.w;
            sW[(kk + 4) * BN + n] = w1.x; sW[(kk + 5) * BN + n] = w1.y;
            sW[(kk + 6) * BN + n] = w1.z; sW[(kk + 7) * BN + n] = w1.w;
        }
        __syncthreads();

#pragma unroll
        for (int k = 0; k < BK; k++) {
            float a[R];
#pragma unroll
            for (int i = 0; i < R; i++) a[i] = sA[k * BM + ty * R + i];
            float4 w0 = *reinterpret_cast<const float4*>(&sW[k * BN + tx * 8]);
            float4 w1 = *reinterpret_cast<const float4*>(&sW[k * BN + tx * 8 + 4]);
            float w[8] = {w0.x, w0.y, w0.z, w0.w, w1.x, w1.y, w1.z, w1.w};
#pragma unroll
            for (int i = 0; i < R; i++)
#pragma unroll
                for (int j = 0; j < 8; j++)
                    acc[i][j] = fmaf(a[i], w[j], acc[i][j]);
        }
        __syncthreads();
    }

    float b[8];
#pragma unroll
    for (int j = 0; j < 8; j++) b[j] = bias[tx * 8 + j];

#pragma unroll
    for (int i = 0; i < R; i++) {
        int m = m0 + ty * R + i;
        float out[8];
#pragma unroll
        for (int j = 0; j < 8; j++) {
            float v = acc[i][j] + b[j];
            if (ACT == 0) v = (v > 0.0f) ? v : 0.01f * v;
            else          v = tanhf(v);
            out[j] = v;
        }
        float* crow = &C[m * HD + tx * 8];
        *reinterpret_cast<float4*>(crow)     = make_float4(out[0], out[1], out[2], out[3]);
        *reinterpret_cast<float4*>(crow + 4) = make_float4(out[4], out[5], out[6], out[7]);
        if (C2) {
            float* c2row = &C2[m * HD + tx * 8];
            *reinterpret_cast<float4*>(c2row)     = make_float4(out[0], out[1], out[2], out[3]);
            *reinterpret_cast<float4*>(c2row + 4) = make_float4(out[4], out[5], out[6], out[7]);
        }
    }
}

// ---------------------------------------------------------------------------
// K1: stage-1 linears (v: K=64, e: K=32) + full vew1 scan (-> src)
// grid = 64 + 128 + XB_BLOCKS
// ---------------------------------------------------------------------------
__global__ __launch_bounds__(256)
void k1_kernel(const float* __restrict__ atom, const float* __restrict__ bond,
               const float* __restrict__ vW1, const float* __restrict__ vb1,
               const float* __restrict__ eW1, const float* __restrict__ eb1,
               const float* __restrict__ vew1,
               float* __restrict__ tmpv, float* __restrict__ tmpe,
               int* __restrict__ src)
{
    __shared__ float sA[16 * 64];
    __shared__ float sW[16 * 128];
    int b = blockIdx.x;
    if (b < 64)
        gemm_body<64, ATOM_DIM, 0>(atom, vW1, vb1, tmpv, nullptr, b * 64, sA, sW);
    else if (b < 192)
        gemm_body<64, BOND_DIM, 0>(bond, eW1, eb1, tmpe, nullptr, (b - 64) * 64, sA, sW);
    else
        extract_body(vew1, src, b - 192);
}

// ---------------------------------------------------------------------------
// K2: stage-2 linears (tanh) + full vew2 scan (-> dst)
// ---------------------------------------------------------------------------
__global__ __launch_bounds__(256)
void k2_kernel(const float* __restrict__ tmpv, const float* __restrict__ tmpe,
               const float* __restrict__ vW2, const float* __restrict__ vb2,
               const float* __restrict__ eW2, const float* __restrict__ eb2,
               const float* __restrict__ vew2,
               float* __restrict__ hvA, float* __restrict__ hvB,
               float* __restrict__ he, int* __restrict__ dst)
{
    __shared__ float sA[16 * 64];
    __shared__ float sW[16 * 128];
    int b = blockIdx.x;
    if (b < 64)
        gemm_body<64, HD, 1>(tmpv, vW2, vb2, hvA, hvB, b * 64, sA, sW);
    else if (b < 192)
        gemm_body<64, HD, 1>(tmpe, eW2, eb2, he, nullptr, (b - 64) * 64, sA, sW);
    else
        extract_body(vew2, dst, b - 192);
}

// ---------------------------------------------------------------------------
// Per-layer MLP GEMM (BM=32 for 128 blocks)
// ---------------------------------------------------------------------------
__global__ __launch_bounds__(256)
void mlp_kernel(const float* __restrict__ A, const float* __restrict__ W,
                const float* __restrict__ bias,
                float* __restrict__ C, float* __restrict__ C2)
{
    __shared__ float sA[16 * 32];
    __shared__ float sW[16 * 128];
    gemm_body<32, HD, 0>(A, W, bias, C, C2, blockIdx.x * 32, sA, sW);
}

// ---------------------------------------------------------------------------
// Edge op: hv_acc[src[e]] += relu(he[e] + hv[dst[e]])
// 8 edges/block, 32 threads/edge, float4 + vector reduction.
// ---------------------------------------------------------------------------
__global__ __launch_bounds__(256)
void edge_kernel(const float* __restrict__ he, const float* __restrict__ hv,
                 float* __restrict__ hv_acc,
                 const int* __restrict__ src, const int* __restrict__ dst)
{
    int e = blockIdx.x * 8 + (threadIdx.x >> 5);
    int q = threadIdx.x & 31;
    int s = __ldg(&src[e]);
    int d = __ldg(&dst[e]);
    float4 a = *reinterpret_cast<const float4*>(&he[e * HD + q * 4]);
    float4 g = *reinterpret_cast<const float4*>(&hv[d * HD + q * 4]);
    float x = fmaxf(a.x + g.x, 0.0f);
    float y = fmaxf(a.y + g.y, 0.0f);
    float z = fmaxf(a.z + g.z, 0.0f);
    float w = fmaxf(a.w + g.w, 0.0f);
    float* ptr = &hv_acc[s * HD + q * 4];
    asm volatile("red.global.add.v4.f32 [%0], {%1, %2, %3, %4};"
                 :: "l"(ptr), "f"(x), "f"(y), "f"(z), "f"(w) : "memory");
}

// ---------------------------------------------------------------------------
// he_out = [hv[src] | hv[dst] | he]  -> [N_E, 3H], float4 copies
// ---------------------------------------------------------------------------
__global__ __launch_bounds__(96)
void he_out_kernel(const float* __restrict__ hv, const float* __restrict__ he,
                   const int* __restrict__ src, const int* __restrict__ dst,
                   float* __restrict__ out)
{
    int e = blockIdx.x;
    int t = threadIdx.x;          // 0..95
    int seg = t >> 5;             // 0,1,2
    int q   = t & 31;             // float4 index within 128-float segment
    int s = __ldg(&src[e]);
    int d = __ldg(&dst[e]);
    const float4* sp;
    if (seg == 0)      sp = reinterpret_cast<const float4*>(&hv[s * HD]);
    else if (seg == 1) sp = reinterpret_cast<const float4*>(&hv[d * HD]);
    else               sp = reinterpret_cast<const float4*>(&he[e * HD]);
    reinterpret_cast<float4*>(out)[e * 96 + seg * 32 + q] = sp[q];
}

// ---------------------------------------------------------------------------
// Launcher
// ---------------------------------------------------------------------------
extern "C" void kernel_launch(void* const* d_in, const int* in_sizes, int n_in,
                              void* d_out, int out_size)
{
    const float* atom = (const float*)d_in[0];
    const float* bond = (const float*)d_in[1];
    const float* vew1 = (const float*)d_in[2];
    const float* vew2 = (const float*)d_in[3];
    const float* vW1  = (const float*)d_in[4];
    const float* vb1  = (const float*)d_in[5];
    const float* vW2  = (const float*)d_in[6];
    const float* vb2  = (const float*)d_in[7];
    const float* eW1  = (const float*)d_in[8];
    const float* eb1  = (const float*)d_in[9];
    const float* eW2  = (const float*)d_in[10];
    const float* eb2  = (const float*)d_in[11];
    const float* mlpW = (const float*)d_in[12];
    const float* mlpb = (const float*)d_in[13];

    float *tmpv, *tmpe, *he, *hvA, *hvB;
    int *src, *dst;
    cudaGetSymbolAddress((void**)&tmpv, g_tmpv);
    cudaGetSymbolAddress((void**)&tmpe, g_tmpe);
    cudaGetSymbolAddress((void**)&he,   g_he);
    cudaGetSymbolAddress((void**)&hvA,  g_hvA);
    cudaGetSymbolAddress((void**)&hvB,  g_hvB);
    cudaGetSymbolAddress((void**)&src,  g_src);
    cudaGetSymbolAddress((void**)&dst,  g_dst);

    float* hv_out = (float*)d_out;
    float* he_out = (float*)d_out + (long long)N_V * HD;

    // K1: stage-1 linears + vew1 scan (src)
    k1_kernel<<<192 + XB_BLOCKS, 256>>>(atom, bond, vW1, vb1, eW1, eb1,
                                        vew1, tmpv, tmpe, src);
    // K2: stage-2 linears (tanh) + vew2 scan (dst)
    k2_kernel<<<192 + XB_BLOCKS, 256>>>(tmpv, tmpe, vW2, vb2, eW2, eb2,
                                        vew2, hvA, hvB, he, dst);

    // message-passing layers
    for (int l = 0; l < N_LAYER; l++) {
        edge_kernel<<<N_E / 8, 256>>>(he, hvA, hvB, src, dst);
        float* c2 = (l == N_LAYER - 1) ? hv_out : hvB;
        mlp_kernel<<<N_V / 32, 256>>>(hvB, mlpW + (long long)l * HD * HD,
                                      mlpb + (long long)l * HD, hvA, c2);
    }

    he_out_kernel<<<N_E, 96>>>(hvA, he, src, dst, he_out);
}

// round 3
// speedup vs baseline: 1.4714x; 1.1653x over previous
#include <cuda_runtime.h>
#include <cuda_bf16.h>

#define N_V 4096
#define N_E 8192
#define HD  128
#define ATOM_DIM 64
#define BOND_DIM 32
#define N_LAYER 4

#define PB 148                    // persistent blocks (1 per SM)
#define PT 512                    // threads per persistent block
#define NWARP (PB * 16)           // 2368 warps

// ---------------------------------------------------------------------------
// Scratch
// ---------------------------------------------------------------------------
__device__ float g_tmpv[N_V * HD];
__device__ float g_tmpe[N_E * HD];
__device__ float g_he  [N_E * HD];
__device__ float g_hvA [N_V * HD];
__device__ float g_hvB [N_V * HD];
__device__ int   g_src [N_E];
__device__ int   g_dst [N_E];
__device__ unsigned g_count = 0;
__device__ unsigned g_sense = 0;

// ---------------------------------------------------------------------------
// f32x2 packed helpers
// ---------------------------------------------------------------------------
__device__ __forceinline__ unsigned long long pack2(float a, float b) {
    unsigned long long r;
    asm("mov.b64 %0, {%1, %2};" : "=l"(r) : "f"(a), "f"(b));
    return r;
}
__device__ __forceinline__ void fma2(unsigned long long& d,
                                     unsigned long long a, unsigned long long b) {
    asm("fma.rn.f32x2 %0, %1, %2, %0;" : "+l"(d) : "l"(a), "l"(b));
}
__device__ __forceinline__ float2 unpack2(unsigned long long v) {
    float2 r;
    asm("mov.b64 {%0, %1}, %2;" : "=f"(r.x), "=f"(r.y) : "l"(v));
    return r;
}

// ---------------------------------------------------------------------------
// Grid barrier (all PB blocks co-resident: 1 block/SM by construction)
// ---------------------------------------------------------------------------
__device__ __forceinline__ void gsync() {
    __threadfence();
    __syncthreads();
    if (threadIdx.x == 0) {
        unsigned gen = atomicAdd(&g_sense, 0u);
        if (atomicAdd(&g_count, 1u) == PB - 1u) {
            atomicExch(&g_count, 0u);
            __threadfence();
            atomicAdd(&g_sense, 1u);
        } else {
            while (atomicAdd(&g_sense, 0u) == gen) __nanosleep(32);
        }
    }
    __syncthreads();
}

// ---------------------------------------------------------------------------
// One-hot scan: find nonzero row per column of [N_V, N_E] row-major matrix.
// ---------------------------------------------------------------------------
__device__ __forceinline__ void proc_f4(float4 v, int p, int* __restrict__ outp)
{
    if (v.x != 0.0f || v.y != 0.0f || v.z != 0.0f || v.w != 0.0f) {
        int lin = p << 2;
        int row = lin >> 13;
        int col = lin & (N_E - 1);
        if (v.x != 0.0f) outp[col + 0] = row;
        if (v.y != 0.0f) outp[col + 1] = row;
        if (v.z != 0.0f) outp[col + 2] = row;
        if (v.w != 0.0f) outp[col + 3] = row;
    }
}

#define XB_BLOCKS 1024

__device__ void extract_body(const float* __restrict__ mat,
                             int* __restrict__ outp, int xb)
{
    const int PER = N_V * (N_E / 4);          // 8,388,608 float4
    const int T   = XB_BLOCKS * 256;          // 262,144 threads
    const float4* m4 = reinterpret_cast<const float4*>(mat);
    int base = xb * 256 + threadIdx.x;
    for (int i = base; i < PER; i += 8 * T) { // 4 outer iterations
        float4 v[8];
#pragma unroll
        for (int u = 0; u < 8; u++) v[u] = __ldg(&m4[i + u * T]);
#pragma unroll
        for (int u = 0; u < 8; u++) proc_f4(v[u], i + u * T, outp);
    }
}

// ---------------------------------------------------------------------------
// Register-tiled GEMM body for K1/K2 (hidden under the scans):
// C[BM,128] = act(A[BM,K] @ W[128,K]^T + b); ACT 0=leaky, 1=tanh
// ---------------------------------------------------------------------------
template<int K, int ACT>
__device__ __forceinline__ void gemm_body(const float* __restrict__ A,
                                          const float* __restrict__ W,
                                          const float* __restrict__ bias,
                                          float* __restrict__ C,
                                          float* __restrict__ C2,
                                          int m0, float* sA, float* sW)
{
    constexpr int BM = 64, BK = 16, BN = 128;
    const int tid = threadIdx.x;
    const int tx  = tid & 15;
    const int ty  = tid >> 4;

    float acc[4][8];
#pragma unroll
    for (int i = 0; i < 4; i++)
#pragma unroll
        for (int j = 0; j < 8; j++) acc[i][j] = 0.0f;

#pragma unroll
    for (int k0 = 0; k0 < K; k0 += BK) {
        {
            int j0 = tid * 4, m = j0 >> 4, k = j0 & 15;
            float4 a4 = *reinterpret_cast<const float4*>(&A[(m0 + m) * K + k0 + k]);
            sA[(k + 0) * BM + m] = a4.x; sA[(k + 1) * BM + m] = a4.y;
            sA[(k + 2) * BM + m] = a4.z; sA[(k + 3) * BM + m] = a4.w;
        }
        {
            int j0 = tid * 8, n = j0 >> 4, kk = j0 & 15;
            const float* wr = &W[n * K + k0 + kk];
            float4 w0 = *reinterpret_cast<const float4*>(wr);
            float4 w1 = *reinterpret_cast<const float4*>(wr + 4);
            sW[(kk + 0) * BN + n] = w0.x; sW[(kk + 1) * BN + n] = w0.y;
            sW[(kk + 2) * BN + n] = w0.z; sW[(kk + 3) * BN + n] = w0.w;
            sW[(kk + 4) * BN + n] = w1.x; sW[(kk + 5) * BN + n] = w1.y;
            sW[(kk + 6) * BN + n] = w1.z; sW[(kk + 7) * BN + n] = w1.w;
        }
        __syncthreads();
#pragma unroll
        for (int k = 0; k < BK; k++) {
            float a[4];
#pragma unroll
            for (int i = 0; i < 4; i++) a[i] = sA[k * BM + ty * 4 + i];
            float4 w0 = *reinterpret_cast<const float4*>(&sW[k * BN + tx * 8]);
            float4 w1 = *reinterpret_cast<const float4*>(&sW[k * BN + tx * 8 + 4]);
            float w[8] = {w0.x, w0.y, w0.z, w0.w, w1.x, w1.y, w1.z, w1.w};
#pragma unroll
            for (int i = 0; i < 4; i++)
#pragma unroll
                for (int j = 0; j < 8; j++)
                    acc[i][j] = fmaf(a[i], w[j], acc[i][j]);
        }
        __syncthreads();
    }

    float b[8];
#pragma unroll
    for (int j = 0; j < 8; j++) b[j] = bias[tx * 8 + j];

#pragma unroll
    for (int i = 0; i < 4; i++) {
        int m = m0 + ty * 4 + i;
        float out[8];
#pragma unroll
        for (int j = 0; j < 8; j++) {
            float v = acc[i][j] + b[j];
            if (ACT == 0) v = (v > 0.0f) ? v : 0.01f * v;
            else          v = tanhf(v);
            out[j] = v;
        }
        float* crow = &C[m * HD + tx * 8];
        *reinterpret_cast<float4*>(crow)     = make_float4(out[0], out[1], out[2], out[3]);
        *reinterpret_cast<float4*>(crow + 4) = make_float4(out[4], out[5], out[6], out[7]);
        if (C2) {
            float* c2row = &C2[m * HD + tx * 8];
            *reinterpret_cast<float4*>(c2row)     = make_float4(out[0], out[1], out[2], out[3]);
            *reinterpret_cast<float4*>(c2row + 4) = make_float4(out[4], out[5], out[6], out[7]);
        }
    }
}

// K1: stage-1 linears + vew1 scan (src)
__global__ __launch_bounds__(256)
void k1_kernel(const float* __restrict__ atom, const float* __restrict__ bond,
               const float* __restrict__ vW1, const float* __restrict__ vb1,
               const float* __restrict__ eW1, const float* __restrict__ eb1,
               const float* __restrict__ vew1,
               float* __restrict__ tmpv, float* __restrict__ tmpe,
               int* __restrict__ src)
{
    __shared__ float sA[16 * 64];
    __shared__ float sW[16 * 128];
    int b = blockIdx.x;
    if (b < 64)
        gemm_body<ATOM_DIM, 0>(atom, vW1, vb1, tmpv, nullptr, b * 64, sA, sW);
    else if (b < 192)
        gemm_body<BOND_DIM, 0>(bond, eW1, eb1, tmpe, nullptr, (b - 64) * 64, sA, sW);
    else
        extract_body(vew1, src, b - 192);
}

// K2: stage-2 linears (tanh) + vew2 scan (dst)
__global__ __launch_bounds__(256)
void k2_kernel(const float* __restrict__ tmpv, const float* __restrict__ tmpe,
               const float* __restrict__ vW2, const float* __restrict__ vb2,
               const float* __restrict__ eW2, const float* __restrict__ eb2,
               const float* __restrict__ vew2,
               float* __restrict__ hvA, float* __restrict__ hvB,
               float* __restrict__ he, int* __restrict__ dst)
{
    __shared__ float sA[16 * 64];
    __shared__ float sW[16 * 128];
    int b = blockIdx.x;
    if (b < 64)
        gemm_body<HD, 1>(tmpv, vW2, vb2, hvA, hvB, b * 64, sA, sW);
    else if (b < 192)
        gemm_body<HD, 1>(tmpe, eW2, eb2, he, nullptr, (b - 64) * 64, sA, sW);
    else
        extract_body(vew2, dst, b - 192);
}

// ---------------------------------------------------------------------------
// Persistent kernel: 4 x (edge scatter; sync; MLP GEMM; sync) + he_out.
// Dynamic smem: sW 128x128 floats (64KB) + sA 16 warps x 8 rows x 128 (64KB).
// ---------------------------------------------------------------------------
__global__ __launch_bounds__(PT, 1)
void persist_kernel(const float* __restrict__ he,
                    float* __restrict__ hvA, float* __restrict__ hvB,
                    const int* __restrict__ src, const int* __restrict__ dst,
                    const float* __restrict__ mlpW, const float* __restrict__ mlpb,
                    float* __restrict__ hv_out, float* __restrict__ he_out)
{
    extern __shared__ float smem[];
    float* sW = smem;             // 16384 floats
    float* sA = smem + 16384;     // 16384 floats

    const int tid  = threadIdx.x;
    const int wid  = tid >> 5;
    const int lane = tid & 31;
    const int gw   = blockIdx.x * 16 + wid;

    const float4* he4  = reinterpret_cast<const float4*>(he);

    for (int l = 0; l < N_LAYER; l++) {
        // ---- edge phase: hvB[src[e]] += relu(he[e] + hvA[dst[e]]) ----
        for (int e = gw; e < N_E; e += NWARP) {
            int s = __ldg(&src[e]);
            int d = __ldg(&dst[e]);
            float4 a = __ldg(&he4[e * 32 + lane]);
            float4 g = __ldg(reinterpret_cast<const float4*>(hvA) + d * 32 + lane);
            float x = fmaxf(a.x + g.x, 0.0f);
            float y = fmaxf(a.y + g.y, 0.0f);
            float z = fmaxf(a.z + g.z, 0.0f);
            float w = fmaxf(a.w + g.w, 0.0f);
            float* p = &hvB[s * HD + lane * 4];
            asm volatile("red.global.add.v4.f32 [%0], {%1, %2, %3, %4};"
                         :: "l"(p), "f"(x), "f"(y), "f"(z), "f"(w) : "memory");
        }
        gsync();

        // ---- MLP phase: hvA = leaky(hvB @ W_l^T + b); copy to hvB / hv_out ----
        const float* Wl = mlpW + l * (HD * HD);
        const float* bl = mlpb + l * HD;
        float* C  = hvA;
        float* C2 = (l == N_LAYER - 1) ? hv_out : hvB;

        // stage W transposed: sW[k*128 + n] = Wl[n*128 + k]; conflict-free stores
        {
            int n  = tid & 127;
            int kb = (tid >> 7) * 32;
            const float* wr = Wl + n * HD + kb;
#pragma unroll
            for (int j = 0; j < 8; j++) {
                float4 w = __ldg(reinterpret_cast<const float4*>(wr + j * 4));
                int k = kb + j * 4;
                sW[(k + 0) * HD + n] = w.x;
                sW[(k + 1) * HD + n] = w.y;
                sW[(k + 2) * HD + n] = w.z;
                sW[(k + 3) * HD + n] = w.w;
            }
        }
        __syncthreads();

        // warp task: 8 rows x 128 cols; 512 tasks spread 4 per block
        int g = wid * PB + blockIdx.x;          // wid 0..3 cover all 512 groups
        if (g < N_V / 8) {
            int m0   = g * 8;
            int aoff = wid * (8 * HD);
            // stage A rows into this warp's smem slice
            for (int idx = lane; idx < 256; idx += 32) {
                int r = idx >> 5, kq = (idx & 31) * 4;
                *reinterpret_cast<float4*>(&sA[aoff + r * HD + kq]) =
                    __ldg(reinterpret_cast<const float4*>(&hvB[(m0 + r) * HD + kq]));
            }
            __syncwarp();

            const int c0 = lane * 4;
            unsigned long long acc[8][2];
#pragma unroll
            for (int r = 0; r < 8; r++) { acc[r][0] = 0ull; acc[r][1] = 0ull; }

            for (int k0 = 0; k0 < HD; k0 += 4) {
                float4 av[8];
#pragma unroll
                for (int r = 0; r < 8; r++)
                    av[r] = *reinterpret_cast<const float4*>(&sA[aoff + r * HD + k0]);
#pragma unroll
                for (int j = 0; j < 4; j++) {
                    ulonglong2 ww = *reinterpret_cast<const ulonglong2*>(&sW[(k0 + j) * HD + c0]);
#pragma unroll
                    for (int r = 0; r < 8; r++) {
                        float a = (j == 0) ? av[r].x : (j == 1) ? av[r].y
                                : (j == 2) ? av[r].z : av[r].w;
                        unsigned long long aa = pack2(a, a);
                        fma2(acc[r][0], aa, ww.x);
                        fma2(acc[r][1], aa, ww.y);
                    }
                }
            }

            float4 b4 = __ldg(reinterpret_cast<const float4*>(&bl[c0]));
#pragma unroll
            for (int r = 0; r < 8; r++) {
                float2 v0 = unpack2(acc[r][0]);
                float2 v1 = unpack2(acc[r][1]);
                float o0 = v0.x + b4.x; o0 = (o0 > 0.0f) ? o0 : 0.01f * o0;
                float o1 = v0.y + b4.y; o1 = (o1 > 0.0f) ? o1 : 0.01f * o1;
                float o2 = v1.x + b4.z; o2 = (o2 > 0.0f) ? o2 : 0.01f * o2;
                float o3 = v1.y + b4.w; o3 = (o3 > 0.0f) ? o3 : 0.01f * o3;
                float4 o = make_float4(o0, o1, o2, o3);
                *reinterpret_cast<float4*>(&C [(m0 + r) * HD + c0]) = o;
                *reinterpret_cast<float4*>(&C2[(m0 + r) * HD + c0]) = o;
            }
        }
        gsync();
    }

    // ---- he_out = [hv[src] | hv[dst] | he] ----
    const float4* hv4 = reinterpret_cast<const float4*>(hvA);
    float4* out4 = reinterpret_cast<float4*>(he_out);
    for (int e = gw; e < N_E; e += NWARP) {
        int s = __ldg(&src[e]);
        int d = __ldg(&dst[e]);
        out4[e * 96 + lane]      = __ldg(&hv4[s * 32 + lane]);
        out4[e * 96 + 32 + lane] = __ldg(&hv4[d * 32 + lane]);
        out4[e * 96 + 64 + lane] = __ldg(&he4[e * 32 + lane]);
    }
}

// ---------------------------------------------------------------------------
// Launcher
// ---------------------------------------------------------------------------
extern "C" void kernel_launch(void* const* d_in, const int* in_sizes, int n_in,
                              void* d_out, int out_size)
{
    const float* atom = (const float*)d_in[0];
    const float* bond = (const float*)d_in[1];
    const float* vew1 = (const float*)d_in[2];
    const float* vew2 = (const float*)d_in[3];
    const float* vW1  = (const float*)d_in[4];
    const float* vb1  = (const float*)d_in[5];
    const float* vW2  = (const float*)d_in[6];
    const float* vb2  = (const float*)d_in[7];
    const float* eW1  = (const float*)d_in[8];
    const float* eb1  = (const float*)d_in[9];
    const float* eW2  = (const float*)d_in[10];
    const float* eb2  = (const float*)d_in[11];
    const float* mlpW = (const float*)d_in[12];
    const float* mlpb = (const float*)d_in[13];

    float *tmpv, *tmpe, *he, *hvA, *hvB;
    int *src, *dst;
    cudaGetSymbolAddress((void**)&tmpv, g_tmpv);
    cudaGetSymbolAddress((void**)&tmpe, g_tmpe);
    cudaGetSymbolAddress((void**)&he,   g_he);
    cudaGetSymbolAddress((void**)&hvA,  g_hvA);
    cudaGetSymbolAddress((void**)&hvB,  g_hvB);
    cudaGetSymbolAddress((void**)&src,  g_src);
    cudaGetSymbolAddress((void**)&dst,  g_dst);

    float* hv_out = (float*)d_out;
    float* he_out = (float*)d_out + (long long)N_V * HD;

    static bool attr_set = false;
    if (!attr_set) {
        cudaFuncSetAttribute(persist_kernel,
                             cudaFuncAttributeMaxDynamicSharedMemorySize, 131072);
        attr_set = true;
    }

    k1_kernel<<<192 + XB_BLOCKS, 256>>>(atom, bond, vW1, vb1, eW1, eb1,
                                        vew1, tmpv, tmpe, src);
    k2_kernel<<<192 + XB_BLOCKS, 256>>>(tmpv, tmpe, vW2, vb2, eW2, eb2,
                                        vew2, hvA, hvB, he, dst);
    persist_kernel<<<PB, PT, 131072>>>(he, hvA, hvB, src, dst,
                                       mlpW, mlpb, hv_out, he_out);
}

// round 4
// speedup vs baseline: 1.8020x; 1.2247x over previous
#include <cuda_runtime.h>
#include <cuda_bf16.h>

#define N_V 4096
#define N_E 8192
#define HD  128
#define ATOM_DIM 64
#define BOND_DIM 32
#define N_LAYER 4

#define PB 148                    // persistent blocks (1 per SM)
#define PT 512                    // threads per persistent block
#define NWARP (PB * 16)           // 2368 warps

// ---------------------------------------------------------------------------
// Scratch
// ---------------------------------------------------------------------------
__device__ float g_tmpv[N_V * HD];
__device__ float g_tmpe[N_E * HD];
__device__ float g_he  [N_E * HD];
__device__ float g_hvA [N_V * HD];
__device__ float g_hvB [N_V * HD];
__device__ int   g_src [N_E];
__device__ int   g_dst [N_E];
__device__ unsigned g_count = 0;
__device__ volatile unsigned g_sense = 0;

// ---------------------------------------------------------------------------
// f32x2 packed helpers
// ---------------------------------------------------------------------------
__device__ __forceinline__ unsigned long long pack2(float a, float b) {
    unsigned long long r;
    asm("mov.b64 %0, {%1, %2};" : "=l"(r) : "f"(a), "f"(b));
    return r;
}
__device__ __forceinline__ void fma2(unsigned long long& d,
                                     unsigned long long a, unsigned long long b) {
    asm("fma.rn.f32x2 %0, %1, %2, %0;" : "+l"(d) : "l"(a), "l"(b));
}
__device__ __forceinline__ float2 unpack2(unsigned long long v) {
    float2 r;
    asm("mov.b64 {%0, %1}, %2;" : "=f"(r.x), "=f"(r.y) : "l"(v));
    return r;
}

// ---------------------------------------------------------------------------
// Grid barrier: arrival = 1 atomic per block; wait = volatile L2 load poll
// (no atomic-RMW spin -> no LTS atomic-ALU serialization on the hot word).
// ---------------------------------------------------------------------------
__device__ __forceinline__ void gsync() {
    __syncthreads();
    if (threadIdx.x == 0) {
        __threadfence();                       // make prior writes (incl. red.global) visible
        unsigned gen = g_sense;                // volatile read
        if (atomicAdd(&g_count, 1u) == PB - 1u) {
            g_count = 0;                       // reset before flip
            __threadfence();
            g_sense = gen + 1u;                // release
        } else {
            while (g_sense == gen) { __nanosleep(32); }
        }
    }
    __syncthreads();
}

// ---------------------------------------------------------------------------
// One-hot scan: find nonzero row per column of [N_V, N_E] row-major matrix.
// ---------------------------------------------------------------------------
__device__ __forceinline__ void proc_f4(float4 v, int p, int* __restrict__ outp)
{
    if (v.x != 0.0f || v.y != 0.0f || v.z != 0.0f || v.w != 0.0f) {
        int lin = p << 2;
        int row = lin >> 13;
        int col = lin & (N_E - 1);
        if (v.x != 0.0f) outp[col + 0] = row;
        if (v.y != 0.0f) outp[col + 1] = row;
        if (v.z != 0.0f) outp[col + 2] = row;
        if (v.w != 0.0f) outp[col + 3] = row;
    }
}

#define XB_BLOCKS 1024

__device__ void extract_body(const float* __restrict__ mat,
                             int* __restrict__ outp, int xb)
{
    const int PER = N_V * (N_E / 4);          // 8,388,608 float4
    const int T   = XB_BLOCKS * 256;          // 262,144 threads
    const float4* m4 = reinterpret_cast<const float4*>(mat);
    int base = xb * 256 + threadIdx.x;
    for (int i = base; i < PER; i += 8 * T) { // 4 outer iterations
        float4 v[8];
#pragma unroll
        for (int u = 0; u < 8; u++) v[u] = __ldcs(&m4[i + u * T]);   // evict-first streaming
#pragma unroll
        for (int u = 0; u < 8; u++) proc_f4(v[u], i + u * T, outp);
    }
}

// ---------------------------------------------------------------------------
// Register-tiled GEMM body for K1/K2 (hidden under the scans):
// C[64,128] = act(A[64,K] @ W[128,K]^T + b); ACT 0=leaky, 1=tanh
// ---------------------------------------------------------------------------
template<int K, int ACT>
__device__ __forceinline__ void gemm_body(const float* __restrict__ A,
                                          const float* __restrict__ W,
                                          const float* __restrict__ bias,
                                          float* __restrict__ C,
                                          float* __restrict__ C2,
                                          int m0, float* sA, float* sW)
{
    constexpr int BM = 64, BK = 16, BN = 128;
    const int tid = threadIdx.x;
    const int tx  = tid & 15;
    const int ty  = tid >> 4;

    float acc[4][8];
#pragma unroll
    for (int i = 0; i < 4; i++)
#pragma unroll
        for (int j = 0; j < 8; j++) acc[i][j] = 0.0f;

#pragma unroll
    for (int k0 = 0; k0 < K; k0 += BK) {
        {
            int j0 = tid * 4, m = j0 >> 4, k = j0 & 15;
            float4 a4 = *reinterpret_cast<const float4*>(&A[(m0 + m) * K + k0 + k]);
            sA[(k + 0) * BM + m] = a4.x; sA[(k + 1) * BM + m] = a4.y;
            sA[(k + 2) * BM + m] = a4.z; sA[(k + 3) * BM + m] = a4.w;
        }
        {
            int j0 = tid * 8, n = j0 >> 4, kk = j0 & 15;
            const float* wr = &W[n * K + k0 + kk];
            float4 w0 = *reinterpret_cast<const float4*>(wr);
            float4 w1 = *reinterpret_cast<const float4*>(wr + 4);
            sW[(kk + 0) * BN + n] = w0.x; sW[(kk + 1) * BN + n] = w0.y;
            sW[(kk + 2) * BN + n] = w0.z; sW[(kk + 3) * BN + n] = w0.w;
            sW[(kk + 4) * BN + n] = w1.x; sW[(kk + 5) * BN + n] = w1.y;
            sW[(kk + 6) * BN + n] = w1.z; sW[(kk + 7) * BN + n] = w1.w;
        }
        __syncthreads();
#pragma unroll
        for (int k = 0; k < BK; k++) {
            float a[4];
#pragma unroll
            for (int i = 0; i < 4; i++) a[i] = sA[k * BM + ty * 4 + i];
            float4 w0 = *reinterpret_cast<const float4*>(&sW[k * BN + tx * 8]);
            float4 w1 = *reinterpret_cast<const float4*>(&sW[k * BN + tx * 8 + 4]);
            float w[8] = {w0.x, w0.y, w0.z, w0.w, w1.x, w1.y, w1.z, w1.w};
#pragma unroll
            for (int i = 0; i < 4; i++)
#pragma unroll
                for (int j = 0; j < 8; j++)
                    acc[i][j] = fmaf(a[i], w[j], acc[i][j]);
        }
        __syncthreads();
    }

    float b[8];
#pragma unroll
    for (int j = 0; j < 8; j++) b[j] = bias[tx * 8 + j];

#pragma unroll
    for (int i = 0; i < 4; i++) {
        int m = m0 + ty * 4 + i;
        float out[8];
#pragma unroll
        for (int j = 0; j < 8; j++) {
            float v = acc[i][j] + b[j];
            if (ACT == 0) v = (v > 0.0f) ? v : 0.01f * v;
            else          v = tanhf(v);
            out[j] = v;
        }
        float* crow = &C[m * HD + tx * 8];
        *reinterpret_cast<float4*>(crow)     = make_float4(out[0], out[1], out[2], out[3]);
        *reinterpret_cast<float4*>(crow + 4) = make_float4(out[4], out[5], out[6], out[7]);
        if (C2) {
            float* c2row = &C2[m * HD + tx * 8];
            *reinterpret_cast<float4*>(c2row)     = make_float4(out[0], out[1], out[2], out[3]);
            *reinterpret_cast<float4*>(c2row + 4) = make_float4(out[4], out[5], out[6], out[7]);
        }
    }
}

// K1: stage-1 linears + vew1 scan (src)
__global__ __launch_bounds__(256)
void k1_kernel(const float* __restrict__ atom, const float* __restrict__ bond,
               const float* __restrict__ vW1, const float* __restrict__ vb1,
               const float* __restrict__ eW1, const float* __restrict__ eb1,
               const float* __restrict__ vew1,
               float* __restrict__ tmpv, float* __restrict__ tmpe,
               int* __restrict__ src)
{
    __shared__ float sA[16 * 64];
    __shared__ float sW[16 * 128];
    int b = blockIdx.x;
    if (b < 64)
        gemm_body<ATOM_DIM, 0>(atom, vW1, vb1, tmpv, nullptr, b * 64, sA, sW);
    else if (b < 192)
        gemm_body<BOND_DIM, 0>(bond, eW1, eb1, tmpe, nullptr, (b - 64) * 64, sA, sW);
    else
        extract_body(vew1, src, b - 192);
}

// K2: stage-2 linears (tanh) + vew2 scan (dst)
__global__ __launch_bounds__(256)
void k2_kernel(const float* __restrict__ tmpv, const float* __restrict__ tmpe,
               const float* __restrict__ vW2, const float* __restrict__ vb2,
               const float* __restrict__ eW2, const float* __restrict__ eb2,
               const float* __restrict__ vew2,
               float* __restrict__ hvA, float* __restrict__ hvB,
               float* __restrict__ he, int* __restrict__ dst)
{
    __shared__ float sA[16 * 64];
    __shared__ float sW[16 * 128];
    int b = blockIdx.x;
    if (b < 64)
        gemm_body<HD, 1>(tmpv, vW2, vb2, hvA, hvB, b * 64, sA, sW);
    else if (b < 192)
        gemm_body<HD, 1>(tmpe, eW2, eb2, he, nullptr, (b - 64) * 64, sA, sW);
    else
        extract_body(vew2, dst, b - 192);
}

// ---------------------------------------------------------------------------
// Persistent kernel: 4 x (edge scatter; sync; MLP GEMM; sync) + he_out.
// smem: sW 128x128 floats (64KB) + sA 32x128 floats (16KB) = 80KB
// MLP: 128 blocks x 32 rows, 8 warps/block, warp = 4 rows x 128 cols (f32x2).
// ---------------------------------------------------------------------------
__global__ __launch_bounds__(PT, 1)
void persist_kernel(const float* __restrict__ he,
                    float* __restrict__ hvA, float* __restrict__ hvB,
                    const int* __restrict__ src, const int* __restrict__ dst,
                    const float* __restrict__ mlpW, const float* __restrict__ mlpb,
                    float* __restrict__ hv_out, float* __restrict__ he_out)
{
    extern __shared__ float smem[];
    float* sW = smem;             // 16384 floats
    float* sA = smem + 16384;     // 4096 floats

    const int tid  = threadIdx.x;
    const int wid  = tid >> 5;
    const int lane = tid & 31;
    const int gw   = blockIdx.x * 16 + wid;

    const float4* he4 = reinterpret_cast<const float4*>(he);

    for (int l = 0; l < N_LAYER; l++) {
        // ---- edge phase: hvB[src[e]] += relu(he[e] + hvA[dst[e]]) ----
        for (int e = gw; e < N_E; e += NWARP) {
            int s = __ldg(&src[e]);
            int d = __ldg(&dst[e]);
            float4 a = __ldg(&he4[e * 32 + lane]);
            float4 g = __ldg(reinterpret_cast<const float4*>(hvA) + d * 32 + lane);
            float x = fmaxf(a.x + g.x, 0.0f);
            float y = fmaxf(a.y + g.y, 0.0f);
            float z = fmaxf(a.z + g.z, 0.0f);
            float w = fmaxf(a.w + g.w, 0.0f);
            float* p = &hvB[s * HD + lane * 4];
            asm volatile("red.global.add.v4.f32 [%0], {%1, %2, %3, %4};"
                         :: "l"(p), "f"(x), "f"(y), "f"(z), "f"(w) : "memory");
        }
        gsync();

        // ---- MLP phase: hvA = leaky(hvB @ W_l^T + b); copy to hvB / hv_out ----
        if (blockIdx.x < 128) {
            const float* Wl = mlpW + l * (HD * HD);
            const float* bl = mlpb + l * HD;
            float* C  = hvA;
            float* C2 = (l == N_LAYER - 1) ? hv_out : hvB;
            const int m0 = blockIdx.x * 32;

            // stage W transposed: sW[k*128 + n] = Wl[n*128 + k]
            {
                int n  = tid & 127;
                int kb = (tid >> 7) * 32;
                const float* wr = Wl + n * HD + kb;
#pragma unroll
                for (int j = 0; j < 8; j++) {
                    float4 w = __ldg(reinterpret_cast<const float4*>(wr + j * 4));
                    int k = kb + j * 4;
                    sW[(k + 0) * HD + n] = w.x;
                    sW[(k + 1) * HD + n] = w.y;
                    sW[(k + 2) * HD + n] = w.z;
                    sW[(k + 3) * HD + n] = w.w;
                }
            }
            // stage A: 32 rows x 128 cols (1024 float4, 2 per thread)
            {
                const float4* hvB4 = reinterpret_cast<const float4*>(hvB);
                float4* sA4 = reinterpret_cast<float4*>(sA);
#pragma unroll
                for (int idx = tid; idx < 1024; idx += PT)
                    sA4[idx] = __ldg(&hvB4[m0 * 32 + idx]);
            }
            __syncthreads();

            if (wid < 8) {
                const int r0 = wid * 4;        // rows r0..r0+3 (within block tile)
                const int c0 = lane * 4;       // cols c0..c0+3
                unsigned long long acc[4][2];
#pragma unroll
                for (int r = 0; r < 4; r++) { acc[r][0] = 0ull; acc[r][1] = 0ull; }

                for (int k0 = 0; k0 < HD; k0 += 4) {
                    float4 av[4];
#pragma unroll
                    for (int r = 0; r < 4; r++)
                        av[r] = *reinterpret_cast<const float4*>(&sA[(r0 + r) * HD + k0]);
#pragma unroll
                    for (int j = 0; j < 4; j++) {
                        ulonglong2 ww = *reinterpret_cast<const ulonglong2*>(&sW[(k0 + j) * HD + c0]);
#pragma unroll
                        for (int r = 0; r < 4; r++) {
                            float a = (j == 0) ? av[r].x : (j == 1) ? av[r].y
                                    : (j == 2) ? av[r].z : av[r].w;
                            unsigned long long aa = pack2(a, a);
                            fma2(acc[r][0], aa, ww.x);
                            fma2(acc[r][1], aa, ww.y);
                        }
                    }
                }

                float4 b4 = __ldg(reinterpret_cast<const float4*>(&bl[c0]));
#pragma unroll
                for (int r = 0; r < 4; r++) {
                    float2 v0 = unpack2(acc[r][0]);
                    float2 v1 = unpack2(acc[r][1]);
                    float o0 = v0.x + b4.x; o0 = (o0 > 0.0f) ? o0 : 0.01f * o0;
                    float o1 = v0.y + b4.y; o1 = (o1 > 0.0f) ? o1 : 0.01f * o1;
                    float o2 = v1.x + b4.z; o2 = (o2 > 0.0f) ? o2 : 0.01f * o2;
                    float o3 = v1.y + b4.w; o3 = (o3 > 0.0f) ? o3 : 0.01f * o3;
                    float4 o = make_float4(o0, o1, o2, o3);
                    int m = m0 + r0 + r;
                    *reinterpret_cast<float4*>(&C [m * HD + c0]) = o;
                    *reinterpret_cast<float4*>(&C2[m * HD + c0]) = o;
                }
            }
        }
        gsync();
    }

    // ---- he_out = [hv[src] | hv[dst] | he] ----
    const float4* hv4 = reinterpret_cast<const float4*>(hvA);
    float4* out4 = reinterpret_cast<float4*>(he_out);
    for (int e = gw; e < N_E; e += NWARP) {
        int s = __ldg(&src[e]);
        int d = __ldg(&dst[e]);
        out4[e * 96 + lane]      = __ldg(&hv4[s * 32 + lane]);
        out4[e * 96 + 32 + lane] = __ldg(&hv4[d * 32 + lane]);
        out4[e * 96 + 64 + lane] = __ldg(&he4[e * 32 + lane]);
    }
}

// ---------------------------------------------------------------------------
// Launcher
// ---------------------------------------------------------------------------
extern "C" void kernel_launch(void* const* d_in, const int* in_sizes, int n_in,
                              void* d_out, int out_size)
{
    const float* atom = (const float*)d_in[0];
    const float* bond = (const float*)d_in[1];
    const float* vew1 = (const float*)d_in[2];
    const float* vew2 = (const float*)d_in[3];
    const float* vW1  = (const float*)d_in[4];
    const float* vb1  = (const float*)d_in[5];
    const float* vW2  = (const float*)d_in[6];
    const float* vb2  = (const float*)d_in[7];
    const float* eW1  = (const float*)d_in[8];
    const float* eb1  = (const float*)d_in[9];
    const float* eW2  = (const float*)d_in[10];
    const float* eb2  = (const float*)d_in[11];
    const float* mlpW = (const float*)d_in[12];
    const float* mlpb = (const float*)d_in[13];

    float *tmpv, *tmpe, *he, *hvA, *hvB;
    int *src, *dst;
    cudaGetSymbolAddress((void**)&tmpv, g_tmpv);
    cudaGetSymbolAddress((void**)&tmpe, g_tmpe);
    cudaGetSymbolAddress((void**)&he,   g_he);
    cudaGetSymbolAddress((void**)&hvA,  g_hvA);
    cudaGetSymbolAddress((void**)&hvB,  g_hvB);
    cudaGetSymbolAddress((void**)&src,  g_src);
    cudaGetSymbolAddress((void**)&dst,  g_dst);

    float* hv_out = (float*)d_out;
    float* he_out = (float*)d_out + (long long)N_V * HD;

    cudaFuncSetAttribute(persist_kernel,
                         cudaFuncAttributeMaxDynamicSharedMemorySize, 81920);

    k1_kernel<<<192 + XB_BLOCKS, 256>>>(atom, bond, vW1, vb1, eW1, eb1,
                                        vew1, tmpv, tmpe, src);
    k2_kernel<<<192 + XB_BLOCKS, 256>>>(tmpv, tmpe, vW2, vb2, eW2, eb2,
                                        vew2, hvA, hvB, he, dst);
    persist_kernel<<<PB, PT, 81920>>>(he, hvA, hvB, src, dst,
                                      mlpW, mlpb, hv_out, he_out);
}